// round 5
// baseline (speedup 1.0000x reference)
#include <cuda_runtime.h>

// LightweightConv: depthwise temporal conv with per-head softmax weights.
// B=16, T=4000, C=512, H=8, K=31, PAD=15.
// out[b,t,c] = sum_k softmax(w)[c%8][k] * x[b, t-15+k, c] + bias[c%8]
//
// R5: K split into two phases (k=0..15, k=16..30) so only 16 packed weights
// (32 regs) are live at a time -> ~82 regs -> 3 CTAs/SM (occ 22%->33%).
// Phase-B x reloads are L1 hits. Streaming stores protect L2 halo.

#define B_ 16
#define T_ 4000
#define C_ 512
#define H_ 8
#define K_ 31
#define PAD_ 15
#define TT 16   // t-outputs per thread; 4000 / 16 = 250 blocks in t
#define KA 16   // phase-A taps: k in [0,16)
#define KB 15   // phase-B taps: k in [16,31)

// Packed (per channel-pair) softmaxed weights and bias.
// Pair type p in [0,4): channels (2p, 2p+1) mod 8 -> heads (2p, 2p+1).
__device__ unsigned long long g_wpair[4][K_];
__device__ unsigned long long g_bpair[4];

__global__ void prep_kernel(const float* __restrict__ w,
                            const float* __restrict__ bias) {
    __shared__ float ws[H_][K_];
    int tid = threadIdx.x;
    if (tid < H_) {
        float m = -3.402823466e38f;
        #pragma unroll
        for (int k = 0; k < K_; k++) m = fmaxf(m, w[tid * K_ + k]);
        float e[K_];
        float s = 0.0f;
        #pragma unroll
        for (int k = 0; k < K_; k++) {
            e[k] = expf(w[tid * K_ + k] - m);
            s += e[k];
        }
        float inv = 1.0f / s;
        #pragma unroll
        for (int k = 0; k < K_; k++) ws[tid][k] = e[k] * inv;
    }
    __syncthreads();
    if (tid < 4 * K_) {
        int p = tid / K_;
        int k = tid % K_;
        float2 v = make_float2(ws[2 * p][k], ws[2 * p + 1][k]);
        g_wpair[p][k] = *reinterpret_cast<unsigned long long*>(&v);
    }
    if (tid < 4) {
        float2 v = make_float2(bias[2 * tid], bias[2 * tid + 1]);
        g_bpair[tid] = *reinterpret_cast<unsigned long long*>(&v);
    }
}

// Packed fp32x2 FMA (sm_100+): d = a*b + c elementwise on two packed floats.
__device__ __forceinline__ unsigned long long ffma2(unsigned long long a,
                                                    unsigned long long b,
                                                    unsigned long long c) {
    unsigned long long d;
    asm("fma.rn.f32x2 %0, %1, %2, %3;" : "=l"(d) : "l"(a), "l"(b), "l"(c));
    return d;
}

// Streaming 8B store (evict-first: output is never re-read; protect L2 halo).
__device__ __forceinline__ void stcs8(float* a, unsigned long long v) {
    asm volatile("st.global.cs.b64 [%0], %1;" :: "l"(a), "l"(v));
}

__global__ void __launch_bounds__(256, 3)
conv_kernel(const float* __restrict__ x, float* __restrict__ out) {
    const int tid = threadIdx.x;          // 0..255
    const int c0 = tid << 1;              // channels c0, c0+1 (contiguous)
    const int p = tid & 3;                // pair type: heads (2p, 2p+1)
    const int b = blockIdx.y;
    const int t0 = blockIdx.x * TT;

    unsigned long long acc[TT];
    {
        const unsigned long long bb = g_bpair[p];
        #pragma unroll
        for (int j = 0; j < TT; j++) acc[j] = bb;
    }

    const float* xp = x + ((size_t)b * T_) * C_ + c0;
    const bool interior = (t0 >= PAD_ && t0 + TT + PAD_ <= T_);

    // ---- Phase A: taps k = 0..15. Needs x rows i in [0, TT+KA-1). ----
    {
        unsigned long long wa[KA];
        #pragma unroll
        for (int k = 0; k < KA; k++) wa[k] = g_wpair[p][k];

        if (interior) {
            const float* xq = xp + (size_t)(t0 - PAD_) * C_;
            #pragma unroll
            for (int i = 0; i < TT + KA - 1; i++) {
                const unsigned long long xv =
                    *reinterpret_cast<const unsigned long long*>(xq + (size_t)i * C_);
                #pragma unroll
                for (int j = 0; j < TT; j++) {
                    if (i - j >= 0 && i - j < KA)
                        acc[j] = ffma2(wa[i - j], xv, acc[j]);
                }
            }
        } else {
            #pragma unroll
            for (int i = 0; i < TT + KA - 1; i++) {
                const int t = t0 - PAD_ + i;
                unsigned long long xv = 0ull;
                if (t >= 0 && t < T_)
                    xv = *reinterpret_cast<const unsigned long long*>(
                            xp + (size_t)t * C_);
                #pragma unroll
                for (int j = 0; j < TT; j++) {
                    if (i - j >= 0 && i - j < KA)
                        acc[j] = ffma2(wa[i - j], xv, acc[j]);
                }
            }
        }
    }

    // ---- Phase B: taps k = 16..30. Needs x rows i in [KA, TT+K_-1). ----
    {
        unsigned long long wb[KB];
        #pragma unroll
        for (int k = 0; k < KB; k++) wb[k] = g_wpair[p][KA + k];

        if (interior) {
            const float* xq = xp + (size_t)(t0 - PAD_) * C_;
            #pragma unroll
            for (int i = KA; i < TT + K_ - 1; i++) {
                const unsigned long long xv =
                    *reinterpret_cast<const unsigned long long*>(xq + (size_t)i * C_);
                #pragma unroll
                for (int j = 0; j < TT; j++) {
                    if (i - j >= KA && i - j < K_)
                        acc[j] = ffma2(wb[i - j - KA], xv, acc[j]);
                }
            }
        } else {
            #pragma unroll
            for (int i = KA; i < TT + K_ - 1; i++) {
                const int t = t0 - PAD_ + i;
                unsigned long long xv = 0ull;
                if (t >= 0 && t < T_)
                    xv = *reinterpret_cast<const unsigned long long*>(
                            xp + (size_t)t * C_);
                #pragma unroll
                for (int j = 0; j < TT; j++) {
                    if (i - j >= KA && i - j < K_)
                        acc[j] = ffma2(wb[i - j - KA], xv, acc[j]);
                }
            }
        }
    }

    float* op = out + ((size_t)b * T_ + t0) * C_ + c0;
    #pragma unroll
    for (int j = 0; j < TT; j++)
        stcs8(op + (size_t)j * C_, acc[j]);
}

extern "C" void kernel_launch(void* const* d_in, const int* in_sizes, int n_in,
                              void* d_out, int out_size) {
    const float* x    = (const float*)d_in[0];  // (B, T, C)
    const float* w    = (const float*)d_in[1];  // (H, 1, K)
    const float* bias = (const float*)d_in[2];  // (H,)
    float* out = (float*)d_out;                 // (B, T, C)

    prep_kernel<<<1, 128>>>(w, bias);

    dim3 grid(T_ / TT, B_);
    conv_kernel<<<grid, 256>>>(x, out);
}

// round 6
// speedup vs baseline: 1.0326x; 1.0326x over previous
#include <cuda_runtime.h>

// LightweightConv: depthwise temporal conv with per-head softmax weights.
// B=16, T=4000, C=512, H=8, K=31, PAD=15.
// out[b,t,c] = sum_k softmax(w)[c%8][k] * x[b, t-15+k, c] + bias[c%8]
//
// R6: R4 structure (weights resident, unsplit, 2 CTA/SM) with TT=24:
// halo factor 2.25 (was 2.5) -> 10% fewer loads per output. Tail block
// (t0=3984, 16 valid outputs) handled by the boundary path + store guard.

#define B_ 16
#define T_ 4000
#define C_ 512
#define H_ 8
#define K_ 31
#define PAD_ 15
#define TT 24   // t-outputs per thread; ceil(4000/24) = 167 blocks in t

// Packed (per channel-pair) softmaxed weights and bias.
// Pair type p in [0,4): channels (2p, 2p+1) mod 8 -> heads (2p, 2p+1).
__device__ unsigned long long g_wpair[4][K_];
__device__ unsigned long long g_bpair[4];

__global__ void prep_kernel(const float* __restrict__ w,
                            const float* __restrict__ bias) {
    __shared__ float ws[H_][K_];
    int tid = threadIdx.x;
    if (tid < H_) {
        float m = -3.402823466e38f;
        #pragma unroll
        for (int k = 0; k < K_; k++) m = fmaxf(m, w[tid * K_ + k]);
        float e[K_];
        float s = 0.0f;
        #pragma unroll
        for (int k = 0; k < K_; k++) {
            e[k] = expf(w[tid * K_ + k] - m);
            s += e[k];
        }
        float inv = 1.0f / s;
        #pragma unroll
        for (int k = 0; k < K_; k++) ws[tid][k] = e[k] * inv;
    }
    __syncthreads();
    if (tid < 4 * K_) {
        int p = tid / K_;
        int k = tid % K_;
        float2 v = make_float2(ws[2 * p][k], ws[2 * p + 1][k]);
        g_wpair[p][k] = *reinterpret_cast<unsigned long long*>(&v);
    }
    if (tid < 4) {
        float2 v = make_float2(bias[2 * tid], bias[2 * tid + 1]);
        g_bpair[tid] = *reinterpret_cast<unsigned long long*>(&v);
    }
}

// Packed fp32x2 FMA (sm_100+): d = a*b + c elementwise on two packed floats.
__device__ __forceinline__ unsigned long long ffma2(unsigned long long a,
                                                    unsigned long long b,
                                                    unsigned long long c) {
    unsigned long long d;
    asm("fma.rn.f32x2 %0, %1, %2, %3;" : "=l"(d) : "l"(a), "l"(b), "l"(c));
    return d;
}

// Streaming 8B store (evict-first: output is never re-read; protect L2 halo).
__device__ __forceinline__ void stcs8(float* a, unsigned long long v) {
    asm volatile("st.global.cs.b64 [%0], %1;" :: "l"(a), "l"(v));
}

__global__ void __launch_bounds__(256, 2)
conv_kernel(const float* __restrict__ x, float* __restrict__ out) {
    const int tid = threadIdx.x;          // 0..255
    const int c0 = tid << 1;              // channels c0, c0+1 (contiguous)
    const int p = tid & 3;                // pair type: heads (2p, 2p+1)
    const int b = blockIdx.y;
    const int t0 = blockIdx.x * TT;

    // Weights for this channel pair (packed), resident in registers.
    unsigned long long wk[K_];
    #pragma unroll
    for (int k = 0; k < K_; k++) wk[k] = g_wpair[p][k];

    const unsigned long long bb = g_bpair[p];

    unsigned long long acc[TT];
    #pragma unroll
    for (int j = 0; j < TT; j++) acc[j] = bb;

    const float* xp = x + ((size_t)b * T_) * C_ + c0;

    if (t0 >= PAD_ && t0 + TT + PAD_ <= T_) {
        // Interior fast path: no boundary predicates.
        const float* xq = xp + (size_t)(t0 - PAD_) * C_;
        #pragma unroll
        for (int i = 0; i < TT + 2 * PAD_; i++) {
            const unsigned long long xv =
                *reinterpret_cast<const unsigned long long*>(xq + (size_t)i * C_);
            #pragma unroll
            for (int j = 0; j < TT; j++) {
                if (i - j >= 0 && i - j < K_)   // constant-folds after unroll
                    acc[j] = ffma2(wk[i - j], xv, acc[j]);
            }
        }
        float* op = out + ((size_t)b * T_ + t0) * C_ + c0;
        #pragma unroll
        for (int j = 0; j < TT; j++)
            stcs8(op + (size_t)j * C_, acc[j]);
    } else {
        // Boundary path: zero-padded loads, guarded stores (covers tail block).
        #pragma unroll
        for (int i = 0; i < TT + 2 * PAD_; i++) {
            const int t = t0 - PAD_ + i;
            unsigned long long xv = 0ull;
            if (t >= 0 && t < T_)
                xv = *reinterpret_cast<const unsigned long long*>(xp + (size_t)t * C_);
            #pragma unroll
            for (int j = 0; j < TT; j++) {
                if (i - j >= 0 && i - j < K_)
                    acc[j] = ffma2(wk[i - j], xv, acc[j]);
            }
        }
        float* op = out + ((size_t)b * T_ + t0) * C_ + c0;
        #pragma unroll
        for (int j = 0; j < TT; j++)
            if (t0 + j < T_)
                stcs8(op + (size_t)j * C_, acc[j]);
    }
}

extern "C" void kernel_launch(void* const* d_in, const int* in_sizes, int n_in,
                              void* d_out, int out_size) {
    const float* x    = (const float*)d_in[0];  // (B, T, C)
    const float* w    = (const float*)d_in[1];  // (H, 1, K)
    const float* bias = (const float*)d_in[2];  // (H,)
    float* out = (float*)d_out;                 // (B, T, C)

    prep_kernel<<<1, 128>>>(w, bias);

    dim3 grid((T_ + TT - 1) / TT, B_);
    conv_kernel<<<grid, 256>>>(x, out);
}